// round 13
// baseline (speedup 1.0000x reference)
#include <cuda_runtime.h>
#include <cuda_bf16.h>
#include <math.h>

// Compile-time capacity (actual sizes derived at runtime from in_sizes)
#define NMAX   65536
#define EMAX   1048576
#define ETMAX  (EMAX + NMAX)
#define FMAX   128
#define HMAX   4
#define CHUNK  128
#define NEG_SLOPE 0.2f
#define BN_EPS 1e-5f

// ---------------- device scratch (statics; no runtime allocation) ----------
__device__ float g_feat [NMAX * FMAX];          // layer input features
__device__ float g_hw   [NMAX * FMAX];          // x @ W
__device__ float g_agg  [NMAX * FMAX];          // layer-3 pre-logsoftmax
__device__ float g_alsrc[NMAX * HMAX];
__device__ float g_aldst[NMAX * HMAX];
__device__ float g_alpha[(size_t)ETMAX * HMAX]; // per-edge exp(logit)
__device__ int   g_deg  [NMAX];                 // in-degree per dst
__device__ int   g_off  [NMAX + 1];             // CSR offsets
__device__ int   g_cur  [NMAX];                 // scatter cursors
__device__ int   g_esrc [ETMAX];                // src node per CSR slot

// ---------------- CSR build (verified in R12; unchanged) -------------------
__global__ void k_zero_deg(int n) {
    int i = blockIdx.x * blockDim.x + threadIdx.x;
    if (i < n) g_deg[i] = 0;
}

__global__ void k_hist(const int* __restrict__ ei, int E, int ET) {
    int e = blockIdx.x * blockDim.x + threadIdx.x;
    if (e >= ET) return;
    int d = (e < E) ? ei[E + e] : (e - E);
    atomicAdd(&g_deg[d], 1);
}

__global__ void k_scan(int n) {
    __shared__ int sh[1024];
    int t = threadIdx.x;
    int chunk = (n + 1023) / 1024;
    int lo = min(t * chunk, n), hi = min(lo + chunk, n);
    int sum = 0;
    for (int i = lo; i < hi; i++) sum += g_deg[i];
    sh[t] = sum;
    __syncthreads();
    if (t == 0) {
        int run = 0;
        for (int i = 0; i < 1024; i++) { int v = sh[i]; sh[i] = run; run += v; }
    }
    __syncthreads();
    int base = sh[t];
    for (int i = lo; i < hi; i++) {
        g_off[i] = base;
        g_cur[i] = base;
        base += g_deg[i];
    }
    if (hi == n) g_off[n] = base;
}

__global__ void k_scatter(const int* __restrict__ ei, int E, int ET) {
    int e = blockIdx.x * blockDim.x + threadIdx.x;
    if (e >= ET) return;
    int s, d;
    if (e < E) { s = ei[e]; d = ei[E + e]; }
    else       { s = d = e - E; }
    int p = atomicAdd(&g_cur[d], 1);
    g_esrc[p] = s;
}

// ---------------- GEMM + attention-logit epilogue --------------------------
// Y[n,Fout] = X[n,Fin] @ W[Fin,Fout]; then alsrc/aldst from the shared tile.
__global__ void k_gemm_al(const float* __restrict__ X, const float* __restrict__ W,
                          float* __restrict__ Y,
                          const float* __restrict__ a_src, const float* __restrict__ a_dst,
                          int n, int Fin, int Fout, int H, int C) {
    __shared__ float xs[32][FMAX + 1];
    int row0 = blockIdx.x * 32;
    int j = threadIdx.x;                  // blockDim.x = 128
    int rows = min(32, n - row0);
    for (int idx = j; idx < 32 * Fin; idx += blockDim.x) {
        int r = idx / Fin, k = idx - r * Fin;
        xs[r][k] = (r < rows) ? X[(size_t)(row0 + r) * Fin + k] : 0.f;
    }
    __syncthreads();
    float acc[32];
#pragma unroll
    for (int i = 0; i < 32; i++) acc[i] = 0.f;
    if (j < Fout) {
        int k = 0;
        for (; k + 4 <= Fin; k += 4) {    // unroll-4: 4 outstanding LDGs
            float w0 = W[(size_t)(k + 0) * Fout + j];
            float w1 = W[(size_t)(k + 1) * Fout + j];
            float w2 = W[(size_t)(k + 2) * Fout + j];
            float w3 = W[(size_t)(k + 3) * Fout + j];
#pragma unroll
            for (int i = 0; i < 32; i++)
                acc[i] += xs[i][k] * w0 + xs[i][k + 1] * w1
                        + xs[i][k + 2] * w2 + xs[i][k + 3] * w3;
        }
        for (; k < Fin; k++) {
            float w = W[(size_t)k * Fout + j];
#pragma unroll
            for (int i = 0; i < 32; i++) acc[i] += xs[i][k] * w;
        }
        for (int i = 0; i < rows; i++)
            Y[(size_t)(row0 + i) * Fout + j] = acc[i];
    }
    // ---- epilogue: attention logits from the output tile (reuse xs) ----
    __syncthreads();                      // all xs (input) reads done
    if (j < Fout)
        for (int i = 0; i < 32; i++) xs[i][j] = acc[i];
    __syncthreads();
    for (int t = j; t < 32 * H; t += blockDim.x) {
        int r = t / H, h = t - r * H;
        if (r < rows) {
            float vs = 0.f, vd = 0.f;
            for (int c = 0; c < C; c++) {
                float xv = xs[r][h * C + c];
                vs += xv * a_src[h * C + c];
                vd += xv * a_dst[h * C + c];
            }
            g_alsrc[(row0 + r) * H + h] = vs;
            g_aldst[(row0 + r) * H + h] = vd;
        }
    }
}

// ---------------- fused softmax + gather + bias/relu/BN --------------------
// One block (128 threads) per dst node.
// Phase 1 (edge-parallel): ex = exp(leaky_relu(logit)) -> g_alpha, denom via
//   register partials + shared atomics. No max-shift (logits << 88: exact).
// Phase 2 (feature-parallel): chunked shared staging of src + normalized
//   alpha, independent hw row loads -> high MLP, no global atomics.
__global__ void k_attn_agg(const float* __restrict__ hw, float* __restrict__ outp,
                           const float* __restrict__ bias,
                           const float* __restrict__ bn_g, const float* __restrict__ bn_b,
                           const float* __restrict__ bn_m, const float* __restrict__ bn_v,
                           int F, int H, int C, int do_post) {
    int d = blockIdx.x;
    int j = threadIdx.x;                  // blockDim.x = 128
    int lo = g_off[d], hi = g_off[d + 1];
    int deg = hi - lo;
    __shared__ float s_den[HMAX];
    __shared__ float s_rden[HMAX];
    __shared__ int   s_src[CHUNK];
    __shared__ float s_alpha[CHUNK][HMAX];
    if (j < H) s_den[j] = 0.f;
    __syncthreads();

    float ad[HMAX], dloc[HMAX];
#pragma unroll
    for (int h = 0; h < HMAX; h++) {
        dloc[h] = 0.f;
        ad[h] = (h < H) ? g_aldst[d * H + h] : 0.f;
    }
    for (int e = lo + j; e < hi; e += blockDim.x) {
        int s = g_esrc[e];
#pragma unroll
        for (int h = 0; h < HMAX; h++) if (h < H) {
            float l = g_alsrc[s * H + h] + ad[h];
            l = (l > 0.f) ? l : NEG_SLOPE * l;
            float ex = __expf(l);
            g_alpha[(size_t)e * H + h] = ex;
            dloc[h] += ex;
        }
    }
    if (j < deg) {                        // only threads that touched edges
#pragma unroll
        for (int h = 0; h < HMAX; h++)
            if (h < H) atomicAdd(&s_den[h], dloc[h]);
    }
    __syncthreads();
    if (j < H) s_rden[j] = 1.f / (s_den[j] + 1e-16f);

    int hh = (j < F) ? j / C : 0;
    float acc = 0.f;
    for (int base = lo; base < hi; base += CHUNK) {
        int cnt = min(CHUNK, hi - base);
        __syncthreads();                  // protect shared reuse across chunks
        if (j < cnt) {
            int e = base + j;
            s_src[j] = g_esrc[e];
#pragma unroll
            for (int h = 0; h < HMAX; h++)
                if (h < H) s_alpha[j][h] = g_alpha[(size_t)e * H + h] * s_rden[h];
        }
        __syncthreads();
        if (j < F) {
            for (int i = 0; i < cnt; i++)
                acc += hw[(size_t)s_src[i] * F + j] * s_alpha[i][hh];
        }
    }
    if (j < F) {
        float x = acc + bias[j];          // gat_conv: out + b
        if (do_post) {                    // relu then BN (eval)
            x = fmaxf(x, 0.f);
            x = (x - bn_m[j]) * rsqrtf(bn_v[j] + BN_EPS) * bn_g[j] + bn_b[j];
        }
        outp[(size_t)d * F + j] = x;
    }
}

// ---------------- log_softmax (input already biased) -----------------------
__global__ void k_lsm(const float* __restrict__ agg, float* __restrict__ out,
                      int n, int dout) {
    int node = blockIdx.x * blockDim.x + threadIdx.x;
    if (node >= n) return;
    const float* row = agg + (size_t)node * dout;
    float mx = -1e30f;
    for (int t = 0; t < dout; t++) mx = fmaxf(mx, row[t]);
    float sm = 0.f;
    for (int t = 0; t < dout; t++) sm += __expf(row[t] - mx);
    float lse = mx + logf(sm);
    for (int t = 0; t < dout; t++)
        out[(size_t)node * dout + t] = row[t] - lse;
}

extern "C" void kernel_launch(void* const* d_in, const int* in_sizes, int n_in,
                              void* d_out, int out_size) {
    const float* x     = (const float*)d_in[0];
    const int*   ei    = (const int*)  d_in[1];
    const float* W1    = (const float*)d_in[2];
    const float* as1   = (const float*)d_in[3];
    const float* ad1   = (const float*)d_in[4];
    const float* b1    = (const float*)d_in[5];
    const float* W2    = (const float*)d_in[6];
    const float* as2   = (const float*)d_in[7];
    const float* ad2   = (const float*)d_in[8];
    const float* b2    = (const float*)d_in[9];
    const float* W3    = (const float*)d_in[10];
    const float* as3   = (const float*)d_in[11];
    const float* ad3   = (const float*)d_in[12];
    const float* b3    = (const float*)d_in[13];
    const float* bn1g  = (const float*)d_in[14];
    const float* bn1b  = (const float*)d_in[15];
    const float* bn1m  = (const float*)d_in[16];
    const float* bn1v  = (const float*)d_in[17];
    const float* bn2g  = (const float*)d_in[18];
    const float* bn2b  = (const float*)d_in[19];
    const float* bn2m  = (const float*)d_in[20];
    const float* bn2v  = (const float*)d_in[21];
    float* out = (float*)d_out;

    // ---- derive actual sizes from in_sizes ----
    int F     = in_sizes[5];                // b1: HEADS*HID
    int DIN   = in_sizes[2] / F;            // W1: (D_IN, F)
    int N     = in_sizes[0] / DIN;          // x:  (N, D_IN)
    int E     = in_sizes[1] / 2;            // edge_index: (2, E)
    int DOUTn = in_sizes[13];               // b3: (D_OUT,)
    int H     = 4;                          // HEADS fixed by model family
    int C     = F / H;
    int ET    = E + N;

    // ---- build CSR once (graph identical across layers) ----
    k_zero_deg<<<(N + 255) / 256, 256>>>(N);
    k_hist<<<(ET + 255) / 256, 256>>>(ei, E, ET);
    k_scan<<<1, 1024>>>(N);
    k_scatter<<<(ET + 255) / 256, 256>>>(ei, E, ET);

    int gb = (N + 31) / 32;
    // ---- layer 1 ----
    k_gemm_al<<<gb, 128>>>(x, W1, g_hw, as1, ad1, N, DIN, F, H, C);
    k_attn_agg<<<N, 128>>>(g_hw, g_feat, b1, bn1g, bn1b, bn1m, bn1v, F, H, C, 1);
    // ---- layer 2 ----
    k_gemm_al<<<gb, 128>>>(g_feat, W2, g_hw, as2, ad2, N, F, F, H, C);
    k_attn_agg<<<N, 128>>>(g_hw, g_feat, b2, bn2g, bn2b, bn2m, bn2v, F, H, C, 1);
    // ---- layer 3 ----
    k_gemm_al<<<gb, 128>>>(g_feat, W3, g_hw, as3, ad3, N, F, DOUTn, 1, DOUTn);
    k_attn_agg<<<N, 128>>>(g_hw, g_agg, b3, b3, b3, b3, b3, DOUTn, 1, DOUTn, 0);
    k_lsm<<<(N + 127) / 128, 128>>>(g_agg, out, N, DOUTn);
}

// round 15
// speedup vs baseline: 1.0833x; 1.0833x over previous
#include <cuda_runtime.h>
#include <cuda_bf16.h>
#include <math.h>

// Problem dims (fixed for this problem; verified against in_sizes since R8)
#define FDIM   128      // HEADS*HID, also D_IN and Fin of every layer
#define HEADS  4
#define HIDC   32
#define DOUTN  40
#define NMAX   65536
#define EMAX   1048576
#define ETMAX  (EMAX + NMAX)
#define CHUNK  128
#define NEG_SLOPE 0.2f
#define BN_EPS 1e-5f

// ---------------- device scratch (statics; no runtime allocation) ----------
__device__ float g_feat [NMAX * FDIM];
__device__ float g_hw   [NMAX * FDIM];
__device__ float g_agg  [NMAX * FDIM];
__device__ float g_alsrc[NMAX * HEADS];
__device__ float g_aldst[NMAX * HEADS];
__device__ float g_alpha[(size_t)ETMAX * HEADS];
__device__ int   g_deg  [NMAX];
__device__ int   g_off  [NMAX + 1];
__device__ int   g_cur  [NMAX];
__device__ int   g_esrc [ETMAX];

// ---------------- CSR build (verified; unchanged) --------------------------
__global__ void k_zero_deg(int n) {
    int i = blockIdx.x * blockDim.x + threadIdx.x;
    if (i < n) g_deg[i] = 0;
}

__global__ void k_hist(const int* __restrict__ ei, int E, int ET) {
    int e = blockIdx.x * blockDim.x + threadIdx.x;
    if (e >= ET) return;
    int d = (e < E) ? ei[E + e] : (e - E);
    atomicAdd(&g_deg[d], 1);
}

__global__ void k_scan(int n) {
    __shared__ int sh[1024];
    int t = threadIdx.x;
    int chunk = (n + 1023) / 1024;
    int lo = min(t * chunk, n), hi = min(lo + chunk, n);
    int sum = 0;
    for (int i = lo; i < hi; i++) sum += g_deg[i];
    sh[t] = sum;
    __syncthreads();
    if (t == 0) {
        int run = 0;
        for (int i = 0; i < 1024; i++) { int v = sh[i]; sh[i] = run; run += v; }
    }
    __syncthreads();
    int base = sh[t];
    for (int i = lo; i < hi; i++) {
        g_off[i] = base;
        g_cur[i] = base;
        base += g_deg[i];
    }
    if (hi == n) g_off[n] = base;
}

__global__ void k_scatter(const int* __restrict__ ei, int E, int ET) {
    int e = blockIdx.x * blockDim.x + threadIdx.x;
    if (e >= ET) return;
    int s, d;
    if (e < E) { s = ei[e]; d = ei[E + e]; }
    else       { s = d = e - E; }
    int p = atomicAdd(&g_cur[d], 1);
    g_esrc[p] = s;
}

// ---------------- GEMM + attention-logit epilogue (compile-time dims) ------
template<int FIN, int FOUT, int H, int C>
__global__ void __launch_bounds__(128)
k_gemm_al(const float* __restrict__ X, const float* __restrict__ W,
          float* __restrict__ Y,
          const float* __restrict__ a_src, const float* __restrict__ a_dst,
          int n) {
    __shared__ float xs[32][FIN + 1];
    int row0 = blockIdx.x * 32;
    int j = threadIdx.x;                  // 128 threads
    int rows = min(32, n - row0);
#pragma unroll 4
    for (int idx = j; idx < 32 * FIN; idx += 128) {
        int r = idx / FIN, k = idx - r * FIN;
        xs[r][k] = (r < rows) ? X[(size_t)(row0 + r) * FIN + k] : 0.f;
    }
    __syncthreads();
    float acc[32];
#pragma unroll
    for (int i = 0; i < 32; i++) acc[i] = 0.f;
    if (j < FOUT) {
#pragma unroll 8
        for (int k = 0; k < FIN; k++) {   // unrolled x8 -> 8 outstanding LDGs
            float w = W[(size_t)k * FOUT + j];
#pragma unroll
            for (int i = 0; i < 32; i++) acc[i] += xs[i][k] * w;
        }
        for (int i = 0; i < rows; i++)
            Y[(size_t)(row0 + i) * FOUT + j] = acc[i];
    }
    // ---- epilogue: attention logits from the output tile (reuse xs) ----
    __syncthreads();
    if (j < FOUT)
#pragma unroll
        for (int i = 0; i < 32; i++) xs[i][j] = acc[i];
    __syncthreads();
    for (int t = j; t < 32 * H; t += 128) {
        int r = t / H, h = t - r * H;
        if (r < rows) {
            float vs = 0.f, vd = 0.f;
#pragma unroll
            for (int c = 0; c < C; c++) {
                float xv = xs[r][h * C + c];
                vs += xv * a_src[h * C + c];
                vd += xv * a_dst[h * C + c];
            }
            g_alsrc[(row0 + r) * H + h] = vs;
            g_aldst[(row0 + r) * H + h] = vd;
        }
    }
}

// ---------------- fused softmax + gather + bias/relu/BN --------------------
// One block (128 threads) per dst. Verified structure from R13; loops are now
// compile-time and H==4 paths use float4 on alsrc/alpha (16B-aligned layout).
template<int F, int H, int C, int POST>
__global__ void __launch_bounds__(128)
k_attn_agg(const float* __restrict__ hw, float* __restrict__ outp,
           const float* __restrict__ bias,
           const float* __restrict__ bn_g, const float* __restrict__ bn_b,
           const float* __restrict__ bn_m, const float* __restrict__ bn_v) {
    int d = blockIdx.x;
    int j = threadIdx.x;
    int lo = g_off[d], hi = g_off[d + 1];
    int deg = hi - lo;
    __shared__ float s_den[H];
    __shared__ float s_rden[H];
    __shared__ int   s_src[CHUNK];
    __shared__ float s_alpha[CHUNK][H];
    if (j < H) s_den[j] = 0.f;
    __syncthreads();

    float ad[H], dloc[H];
    if (H == 4) {
        float4 v = *(const float4*)&g_aldst[d * 4];
        ad[0] = v.x; ad[1] = v.y; ad[2] = v.z; ad[3] = v.w;
    } else {
        ad[0] = g_aldst[d];
    }
#pragma unroll
    for (int h = 0; h < H; h++) dloc[h] = 0.f;

    for (int e = lo + j; e < hi; e += 128) {
        int s = g_esrc[e];
        if (H == 4) {
            float4 as = *(const float4*)&g_alsrc[s * 4];
            float l0 = as.x + ad[0], l1 = as.y + ad[1];
            float l2 = as.z + ad[2], l3 = as.w + ad[3];
            l0 = (l0 > 0.f) ? l0 : NEG_SLOPE * l0;
            l1 = (l1 > 0.f) ? l1 : NEG_SLOPE * l1;
            l2 = (l2 > 0.f) ? l2 : NEG_SLOPE * l2;
            l3 = (l3 > 0.f) ? l3 : NEG_SLOPE * l3;
            float4 ex = make_float4(__expf(l0), __expf(l1), __expf(l2), __expf(l3));
            *(float4*)&g_alpha[(size_t)e * 4] = ex;
            dloc[0] += ex.x; dloc[1] += ex.y; dloc[2] += ex.z; dloc[3] += ex.w;
        } else {
            float l = g_alsrc[s] + ad[0];
            l = (l > 0.f) ? l : NEG_SLOPE * l;
            float ex = __expf(l);
            g_alpha[e] = ex;
            dloc[0] += ex;
        }
    }
    if (j < deg) {
#pragma unroll
        for (int h = 0; h < H; h++) atomicAdd(&s_den[h], dloc[h]);
    }
    __syncthreads();
    if (j < H) s_rden[j] = 1.f / (s_den[j] + 1e-16f);

    constexpr int HH_ = (H == 4) ? 4 : 1;
    int hh = (j < F) ? j / C : 0;
    float acc = 0.f;
    for (int base = lo; base < hi; base += CHUNK) {
        int cnt = min(CHUNK, hi - base);
        __syncthreads();
        if (j < cnt) {
            int e = base + j;
            s_src[j] = g_esrc[e];
            if (HH_ == 4) {
                float4 a = *(const float4*)&g_alpha[(size_t)e * 4];
                s_alpha[j][0] = a.x * s_rden[0];
                s_alpha[j][1] = a.y * s_rden[1];
                s_alpha[j][2] = a.z * s_rden[2];
                s_alpha[j][3] = a.w * s_rden[3];
            } else {
                s_alpha[j][0] = g_alpha[e] * s_rden[0];
            }
        }
        __syncthreads();
        if (j < F) {
#pragma unroll 4
            for (int i = 0; i < cnt; i++)
                acc += hw[(size_t)s_src[i] * F + j] * s_alpha[i][hh];
        }
    }
    if (j < F) {
        float x = acc + bias[j];
        if (POST) {
            x = fmaxf(x, 0.f);
            x = (x - bn_m[j]) * rsqrtf(bn_v[j] + BN_EPS) * bn_g[j] + bn_b[j];
        }
        outp[(size_t)d * F + j] = x;
    }
}

// ---------------- log_softmax over DOUTN (input already biased) ------------
__global__ void k_lsm(const float* __restrict__ agg, float* __restrict__ out,
                      int n) {
    int node = blockIdx.x * blockDim.x + threadIdx.x;
    if (node >= n) return;
    const float* row = agg + (size_t)node * DOUTN;
    float mx = -1e30f;
#pragma unroll 8
    for (int t = 0; t < DOUTN; t++) mx = fmaxf(mx, row[t]);
    float sm = 0.f;
#pragma unroll 8
    for (int t = 0; t < DOUTN; t++) sm += __expf(row[t] - mx);
    float lse = mx + logf(sm);
#pragma unroll 8
    for (int t = 0; t < DOUTN; t++)
        out[(size_t)node * DOUTN + t] = row[t] - lse;
}

extern "C" void kernel_launch(void* const* d_in, const int* in_sizes, int n_in,
                              void* d_out, int out_size) {
    const float* x     = (const float*)d_in[0];
    const int*   ei    = (const int*)  d_in[1];
    const float* W1    = (const float*)d_in[2];
    const float* as1   = (const float*)d_in[3];
    const float* ad1   = (const float*)d_in[4];
    const float* b1    = (const float*)d_in[5];
    const float* W2    = (const float*)d_in[6];
    const float* as2   = (const float*)d_in[7];
    const float* ad2   = (const float*)d_in[8];
    const float* b2    = (const float*)d_in[9];
    const float* W3    = (const float*)d_in[10];
    const float* as3   = (const float*)d_in[11];
    const float* ad3   = (const float*)d_in[12];
    const float* b3    = (const float*)d_in[13];
    const float* bn1g  = (const float*)d_in[14];
    const float* bn1b  = (const float*)d_in[15];
    const float* bn1m  = (const float*)d_in[16];
    const float* bn1v  = (const float*)d_in[17];
    const float* bn2g  = (const float*)d_in[18];
    const float* bn2b  = (const float*)d_in[19];
    const float* bn2m  = (const float*)d_in[20];
    const float* bn2v  = (const float*)d_in[21];
    float* out = (float*)d_out;

    int F   = in_sizes[5];                 // 128 (sanity-checked dims)
    int DIN = in_sizes[2] / F;             // 128
    int N   = in_sizes[0] / DIN;
    int E   = in_sizes[1] / 2;
    int ET  = E + N;

    int gb = (N + 31) / 32;
    // ---- CSR build; gemm_al(L1) placed 4th so ncu (overall launch #5,
    //      = ours #3 after the harness's 2 prefix launches) profiles it ----
    k_zero_deg<<<(N + 255) / 256, 256>>>(N);
    k_hist<<<(ET + 255) / 256, 256>>>(ei, E, ET);
    k_scan<<<1, 1024>>>(N);
    k_gemm_al<FDIM, FDIM, HEADS, HIDC><<<gb, 128>>>(x, W1, g_hw, as1, ad1, N);  // profiled
    k_scatter<<<(ET + 255) / 256, 256>>>(ei, E, ET);

    // ---- layer 1 (gemm already done) ----
    k_attn_agg<FDIM, HEADS, HIDC, 1><<<N, 128>>>(g_hw, g_feat, b1,
                                                 bn1g, bn1b, bn1m, bn1v);
    // ---- layer 2 ----
    k_gemm_al<FDIM, FDIM, HEADS, HIDC><<<gb, 128>>>(g_feat, W2, g_hw, as2, ad2, N);
    k_attn_agg<FDIM, HEADS, HIDC, 1><<<N, 128>>>(g_hw, g_feat, b2,
                                                 bn2g, bn2b, bn2m, bn2v);
    // ---- layer 3 ----
    k_gemm_al<FDIM, DOUTN, 1, DOUTN><<<gb, 128>>>(g_feat, W3, g_hw, as3, ad3, N);
    k_attn_agg<DOUTN, 1, DOUTN, 0><<<N, 128>>>(g_hw, g_agg, b3, b3, b3, b3, b3);
    k_lsm<<<(N + 127) / 128, 128>>>(g_agg, out, N);
}

// round 16
// speedup vs baseline: 1.2138x; 1.1204x over previous
#include <cuda_runtime.h>
#include <cuda_bf16.h>
#include <math.h>

// Problem dims (fixed; verified against in_sizes since R8)
#define FDIM   128
#define HEADS  4
#define HIDC   32
#define DOUTN  40
#define NMAX   65536
#define EMAX   1048576
#define ETMAX  (EMAX + NMAX)
#define NEG_SLOPE 0.2f
#define BN_EPS 1e-5f

// ---------------- device scratch ----------------
__device__ float g_feat [NMAX * FDIM];
__device__ float g_hw   [NMAX * FDIM];
__device__ float g_agg  [NMAX * FDIM];
__device__ float g_alsrc[NMAX * HEADS];
__device__ float g_aldst[NMAX * HEADS];
__device__ float g_alpha[(size_t)ETMAX * HEADS];
__device__ int   g_deg  [NMAX];
__device__ int   g_off  [NMAX + 1];
__device__ int   g_cur  [NMAX];
__device__ int   g_esrc [ETMAX];

// ---------------- CSR build (verified; unchanged) --------------------------
__global__ void k_zero_deg(int n) {
    int i = blockIdx.x * blockDim.x + threadIdx.x;
    if (i < n) g_deg[i] = 0;
}

__global__ void k_hist(const int* __restrict__ ei, int E, int ET) {
    int e = blockIdx.x * blockDim.x + threadIdx.x;
    if (e >= ET) return;
    int d = (e < E) ? ei[E + e] : (e - E);
    atomicAdd(&g_deg[d], 1);
}

__global__ void k_scan(int n) {
    __shared__ int sh[1024];
    int t = threadIdx.x;
    int chunk = (n + 1023) / 1024;
    int lo = min(t * chunk, n), hi = min(lo + chunk, n);
    int sum = 0;
    for (int i = lo; i < hi; i++) sum += g_deg[i];
    sh[t] = sum;
    __syncthreads();
    if (t == 0) {
        int run = 0;
        for (int i = 0; i < 1024; i++) { int v = sh[i]; sh[i] = run; run += v; }
    }
    __syncthreads();
    int base = sh[t];
    for (int i = lo; i < hi; i++) {
        g_off[i] = base;
        g_cur[i] = base;
        base += g_deg[i];
    }
    if (hi == n) g_off[n] = base;
}

__global__ void k_scatter(const int* __restrict__ ei, int E, int ET) {
    int e = blockIdx.x * blockDim.x + threadIdx.x;
    if (e >= ET) return;
    int s, d;
    if (e < E) { s = ei[e]; d = ei[E + e]; }
    else       { s = d = e - E; }
    int p = atomicAdd(&g_cur[d], 1);
    g_esrc[p] = s;
}

// ---------------- GEMM (16-row tile, acc[16]) + attention-logit epilogue ---
template<int FIN, int FOUT, int H, int C>
__global__ void __launch_bounds__(128)
k_gemm_al(const float* __restrict__ X, const float* __restrict__ W,
          float* __restrict__ Y,
          const float* __restrict__ a_src, const float* __restrict__ a_dst,
          int n) {
    __shared__ float xs[16][FIN + 1];
    int row0 = blockIdx.x * 16;
    int j = threadIdx.x;
    int rows = min(16, n - row0);
#pragma unroll 4
    for (int idx = j; idx < 16 * FIN; idx += 128) {
        int r = idx / FIN, k = idx - r * FIN;
        xs[r][k] = (r < rows) ? X[(size_t)(row0 + r) * FIN + k] : 0.f;
    }
    __syncthreads();
    float acc[16];
#pragma unroll
    for (int i = 0; i < 16; i++) acc[i] = 0.f;
    if (j < FOUT) {
#pragma unroll 8
        for (int k = 0; k < FIN; k++) {
            float w = W[(size_t)k * FOUT + j];
#pragma unroll
            for (int i = 0; i < 16; i++) acc[i] += xs[i][k] * w;
        }
        for (int i = 0; i < rows; i++)
            Y[(size_t)(row0 + i) * FOUT + j] = acc[i];
    }
    // ---- epilogue: attention logits from the output tile (reuse xs) ----
    __syncthreads();
    if (j < FOUT)
#pragma unroll
        for (int i = 0; i < 16; i++) xs[i][j] = acc[i];
    __syncthreads();
    for (int t = j; t < 16 * H; t += 128) {
        int r = t / H, h = t - r * H;
        if (r < rows) {
            float vs = 0.f, vd = 0.f;
#pragma unroll
            for (int c = 0; c < C; c++) {
                float xv = xs[r][h * C + c];
                vs += xv * a_src[h * C + c];
                vd += xv * a_dst[h * C + c];
            }
            g_alsrc[(row0 + r) * H + h] = vs;
            g_aldst[(row0 + r) * H + h] = vd;
        }
    }
}

// ---------------- fused softmax + gather + bias/relu/BN: WARP PER DST ------
// 256 threads = 8 warps = 8 dsts per block.
// Phase 1: lane-per-edge exp(leaky_relu) -> g_alpha (float4 for H=4); warp's
//   denom via shared atomics within the warp (+__syncwarp; no cross-warp sync).
// Phase 2: lane owns VPT consecutive feature cols; per edge one vector load
//   per lane, edges unrolled x4 -> 4 outstanding loads per lane.
// No max-shift (logits << 88: exact vs reference's shifted softmax).
template<int F, int H, int C, int POST, int VPT>
__global__ void __launch_bounds__(256)
k_attn_agg(const float* __restrict__ hw, float* __restrict__ outp,
           const float* __restrict__ bias,
           const float* __restrict__ bn_g, const float* __restrict__ bn_b,
           const float* __restrict__ bn_m, const float* __restrict__ bn_v,
           int n) {
    int warp = threadIdx.x >> 5, lane = threadIdx.x & 31;
    int d = blockIdx.x * 8 + warp;
    __shared__ float sden[8][4];
    if (lane < H) sden[warp][lane] = 0.f;
    __syncwarp();
    if (d >= n) return;
    int lo = g_off[d], hi = g_off[d + 1];

    float ad0, ad1, ad2, ad3;
    if (H == 4) {
        float4 v = *(const float4*)&g_aldst[d * 4];
        ad0 = v.x; ad1 = v.y; ad2 = v.z; ad3 = v.w;
    } else {
        ad0 = g_aldst[d]; ad1 = ad2 = ad3 = 0.f;
    }
    // ---- phase 1: lane-per-edge ----
    float p0 = 0.f, p1 = 0.f, p2 = 0.f, p3 = 0.f;
    for (int e = lo + lane; e < hi; e += 32) {
        int s = g_esrc[e];
        if (H == 4) {
            float4 as = *(const float4*)&g_alsrc[s * 4];
            float l0 = as.x + ad0, l1 = as.y + ad1, l2 = as.z + ad2, l3 = as.w + ad3;
            l0 = (l0 > 0.f) ? l0 : NEG_SLOPE * l0;
            l1 = (l1 > 0.f) ? l1 : NEG_SLOPE * l1;
            l2 = (l2 > 0.f) ? l2 : NEG_SLOPE * l2;
            l3 = (l3 > 0.f) ? l3 : NEG_SLOPE * l3;
            float4 ex = make_float4(__expf(l0), __expf(l1), __expf(l2), __expf(l3));
            *(float4*)&g_alpha[(size_t)e * 4] = ex;
            p0 += ex.x; p1 += ex.y; p2 += ex.z; p3 += ex.w;
        } else {
            float l = g_alsrc[s] + ad0;
            l = (l > 0.f) ? l : NEG_SLOPE * l;
            float ex = __expf(l);
            g_alpha[e] = ex;
            p0 += ex;
        }
    }
    if (lo + lane < hi) {                 // lanes that touched >=1 edge
        atomicAdd(&sden[warp][0], p0);
        if (H == 4) {
            atomicAdd(&sden[warp][1], p1);
            atomicAdd(&sden[warp][2], p2);
            atomicAdd(&sden[warp][3], p3);
        }
    }
    __syncwarp();
    // ---- phase 2: lane owns cols [lane*VPT, lane*VPT+VPT) ----
    int col0 = lane * VPT;
    int head = (H == 4) ? (col0 / C) : 0;
    float rden = 1.f / (sden[warp][head] + 1e-16f);
    float acc[VPT];
#pragma unroll
    for (int v = 0; v < VPT; v++) acc[v] = 0.f;
    if (col0 < F) {
        int e = lo;
        for (; e + 4 <= hi; e += 4) {     // 4 edges in flight
#pragma unroll
            for (int u = 0; u < 4; u++) {
                int s = g_esrc[e + u];
                float a = g_alpha[(size_t)(e + u) * H + head] * rden;
                const float* row = hw + (size_t)s * F + col0;
                if (VPT == 4) {
                    float4 v = *(const float4*)row;
                    acc[0] += v.x * a; acc[1] += v.y * a;
                    acc[2] += v.z * a; acc[3] += v.w * a;
                } else {
                    float2 v = *(const float2*)row;
                    acc[0] += v.x * a; acc[1] += v.y * a;
                }
            }
        }
        for (; e < hi; e++) {
            int s = g_esrc[e];
            float a = g_alpha[(size_t)e * H + head] * rden;
            const float* row = hw + (size_t)s * F + col0;
            if (VPT == 4) {
                float4 v = *(const float4*)row;
                acc[0] += v.x * a; acc[1] += v.y * a;
                acc[2] += v.z * a; acc[3] += v.w * a;
            } else {
                float2 v = *(const float2*)row;
                acc[0] += v.x * a; acc[1] += v.y * a;
            }
        }
#pragma unroll
        for (int v = 0; v < VPT; v++) {
            int c = col0 + v;
            float x = acc[v] + bias[c];
            if (POST) {
                x = fmaxf(x, 0.f);
                x = (x - bn_m[c]) * rsqrtf(bn_v[c] + BN_EPS) * bn_g[c] + bn_b[c];
            }
            outp[(size_t)d * F + c] = x;
        }
    }
}

// ---------------- log_softmax over DOUTN (input already biased) ------------
__global__ void k_lsm(const float* __restrict__ agg, float* __restrict__ out,
                      int n) {
    int node = blockIdx.x * blockDim.x + threadIdx.x;
    if (node >= n) return;
    const float* row = agg + (size_t)node * DOUTN;
    float mx = -1e30f;
#pragma unroll 8
    for (int t = 0; t < DOUTN; t++) mx = fmaxf(mx, row[t]);
    float sm = 0.f;
#pragma unroll 8
    for (int t = 0; t < DOUTN; t++) sm += __expf(row[t] - mx);
    float lse = mx + logf(sm);
#pragma unroll 8
    for (int t = 0; t < DOUTN; t++)
        out[(size_t)node * DOUTN + t] = row[t] - lse;
}

extern "C" void kernel_launch(void* const* d_in, const int* in_sizes, int n_in,
                              void* d_out, int out_size) {
    const float* x     = (const float*)d_in[0];
    const int*   ei    = (const int*)  d_in[1];
    const float* W1    = (const float*)d_in[2];
    const float* as1   = (const float*)d_in[3];
    const float* ad1   = (const float*)d_in[4];
    const float* b1    = (const float*)d_in[5];
    const float* W2    = (const float*)d_in[6];
    const float* as2   = (const float*)d_in[7];
    const float* ad2   = (const float*)d_in[8];
    const float* b2    = (const float*)d_in[9];
    const float* W3    = (const float*)d_in[10];
    const float* as3   = (const float*)d_in[11];
    const float* ad3   = (const float*)d_in[12];
    const float* b3    = (const float*)d_in[13];
    const float* bn1g  = (const float*)d_in[14];
    const float* bn1b  = (const float*)d_in[15];
    const float* bn1m  = (const float*)d_in[16];
    const float* bn1v  = (const float*)d_in[17];
    const float* bn2g  = (const float*)d_in[18];
    const float* bn2b  = (const float*)d_in[19];
    const float* bn2m  = (const float*)d_in[20];
    const float* bn2v  = (const float*)d_in[21];
    float* out = (float*)d_out;

    int F   = in_sizes[5];
    int DIN = in_sizes[2] / F;
    int N   = in_sizes[0] / DIN;
    int E   = in_sizes[1] / 2;
    int ET  = E + N;

    int gb = (N + 15) / 16;
    int ab = (N + 7) / 8;
    // gemm_al(L1) kept at launch #4 (the ncu-profiled slot) for a clean A/B
    k_zero_deg<<<(N + 255) / 256, 256>>>(N);
    k_hist<<<(ET + 255) / 256, 256>>>(ei, E, ET);
    k_scan<<<1, 1024>>>(N);
    k_gemm_al<FDIM, FDIM, HEADS, HIDC><<<gb, 128>>>(x, W1, g_hw, as1, ad1, N);  // profiled
    k_scatter<<<(ET + 255) / 256, 256>>>(ei, E, ET);

    // ---- layer 1 ----
    k_attn_agg<FDIM, HEADS, HIDC, 1, 4><<<ab, 256>>>(g_hw, g_feat, b1,
                                                     bn1g, bn1b, bn1m, bn1v, N);
    // ---- layer 2 ----
    k_gemm_al<FDIM, FDIM, HEADS, HIDC><<<gb, 128>>>(g_feat, W2, g_hw, as2, ad2, N);
    k_attn_agg<FDIM, HEADS, HIDC, 1, 4><<<ab, 256>>>(g_hw, g_feat, b2,
                                                     bn2g, bn2b, bn2m, bn2v, N);
    // ---- layer 3 ----
    k_gemm_al<FDIM, DOUTN, 1, DOUTN><<<gb, 128>>>(g_feat, W3, g_hw, as3, ad3, N);
    k_attn_agg<DOUTN, 1, DOUTN, 0, 2><<<ab, 256>>>(g_hw, g_agg, b3,
                                                   b3, b3, b3, b3, N);
    k_lsm<<<(N + 127) / 128, 128>>>(g_agg, out, N);
}